// round 5
// baseline (speedup 1.0000x reference)
#include <cuda_runtime.h>
#include <cuda_bf16.h>

#define NUM_CAMS 200
#define TPB 256
#define PTS_PER_THREAD 8
#define PTS_PER_BLOCK (TPB * PTS_PER_THREAD)

// Per-camera folded transform: row r -> (A0[r], A1[r], A2[r], t[r])
// X_world[r] = d * (x*A0 + y*A1 + A2) + t ;  X_world[3] = 1
__device__ float4 g_cam[NUM_CAMS * 3];

__global__ void precompute_cams_kernel(const float* __restrict__ c2w,   // (C,3,4)
                                       const float* __restrict__ K) {  // (C,3,3)
    int c = blockIdx.x * blockDim.x + threadIdx.x;
    if (c >= NUM_CAMS) return;
    const float* E = c2w + c * 12;
    double f  = (double)K[c * 9 + 0];
    double cx = (double)K[c * 9 + 2];
    double cy = (double)K[c * 9 + 5];
    double invf = 1.0 / f;
#pragma unroll
    for (int r = 0; r < 3; r++) {
        double R0 = (double)E[r * 4 + 0];
        double R1 = (double)E[r * 4 + 1];
        double R2 = (double)E[r * 4 + 2];
        double t  = (double)E[r * 4 + 3];
        float4 p;
        p.x = (float)(R0 * invf);                          // A0
        p.y = (float)(-R1 * invf);                         // A1
        p.z = (float)(-R2 - (cx * R0 - cy * R1) * invf);   // A2
        p.w = (float)t;
        g_cam[c * 3 + r] = p;
    }
}

__global__ __launch_bounds__(TPB)
void project_points_kernel(const int* __restrict__ idx,     // (N,3) c,y,x
                           const float* __restrict__ depth, // (N,)
                           float4* __restrict__ out,        // (N,4)
                           int n) {
    __shared__ float4 scam[NUM_CAMS * 3];
    for (int j = threadIdx.x; j < NUM_CAMS * 3; j += TPB)
        scam[j] = g_cam[j];
    __syncthreads();

    int base = blockIdx.x * PTS_PER_BLOCK + threadIdx.x;
#pragma unroll
    for (int k = 0; k < PTS_PER_THREAD; k++) {
        int i = base + k * TPB;
        if (i < n) {
            int c = idx[3 * i + 0];
            int y = idx[3 * i + 1];
            int x = idx[3 * i + 2];
            float d  = depth[i];
            float fx = (float)x;
            float fy = (float)y;
            float4 p0 = scam[c * 3 + 0];
            float4 p1 = scam[c * 3 + 1];
            float4 p2 = scam[c * 3 + 2];
            float4 o;
            o.x = fmaf(d, fmaf(fx, p0.x, fmaf(fy, p0.y, p0.z)), p0.w);
            o.y = fmaf(d, fmaf(fx, p1.x, fmaf(fy, p1.y, p1.z)), p1.w);
            o.z = fmaf(d, fmaf(fx, p2.x, fmaf(fy, p2.y, p2.z)), p2.w);
            o.w = 1.0f;
            out[i] = o;
        }
    }
}

extern "C" void kernel_launch(void* const* d_in, const int* in_sizes, int n_in,
                              void* d_out, int out_size) {
    // metadata order: point_indices(int32 N*3), depth(f32 N), image_coords(unused),
    //                 camera_to_worlds(f32 C*3*4), intrinsics(f32 C*3*3)
    const int*   idx   = (const int*)d_in[0];
    const float* depth = (const float*)d_in[1];
    const float* c2w   = (const float*)d_in[3];
    const float* K     = (const float*)d_in[4];
    float4* out = (float4*)d_out;
    int n = in_sizes[0] / 3;

    precompute_cams_kernel<<<1, 256>>>(c2w, K);
    int blocks = (n + PTS_PER_BLOCK - 1) / PTS_PER_BLOCK;
    project_points_kernel<<<blocks, TPB>>>(idx, depth, out, n);
}

// round 9
// speedup vs baseline: 1.2087x; 1.2087x over previous
#include <cuda_runtime.h>
#include <cuda_bf16.h>

#define NUM_CAMS 200
#define TPB 256
#define NBLOCKS 888   // 148 SMs * 6 resident blocks -> exactly one balanced wave

// Folded per-camera transform row r: (A0[r], A1[r], A2[r], t[r]) with
// X_world[r] = d * (x*A0 + y*A1 + A2) + t ;  X_world[3] = 1
// Derivation: c2w_full = E_ * n2r * inv(K_), K upper-triangular =>
//   A0 =  R[:,0]/f,  A1 = -R[:,1]/f,  A2 = -R[:,2] - (cx*R[:,0] - cy*R[:,1])/f

__device__ __forceinline__ float4 project_one(const float4* __restrict__ scam,
                                              int c, int y, int x, float d) {
    float fx = (float)x;
    float fy = (float)y;
    float4 p0 = scam[c * 3 + 0];
    float4 p1 = scam[c * 3 + 1];
    float4 p2 = scam[c * 3 + 2];
    float4 o;
    o.x = fmaf(d, fmaf(fx, p0.x, fmaf(fy, p0.y, p0.z)), p0.w);
    o.y = fmaf(d, fmaf(fx, p1.x, fmaf(fy, p1.y, p1.z)), p1.w);
    o.z = fmaf(d, fmaf(fx, p2.x, fmaf(fy, p2.y, p2.z)), p2.w);
    o.w = 1.0f;
    return o;
}

__global__ __launch_bounds__(TPB, 6)
void pointgen_kernel(const int* __restrict__ idx,     // (N,3) c,y,x
                     const float* __restrict__ depth, // (N,)
                     const float* __restrict__ c2w,   // (C,3,4)
                     const float* __restrict__ K,     // (C,3,3)
                     float4* __restrict__ out,        // (N,4)
                     int n) {
    __shared__ float4 scam[NUM_CAMS * 3];

    // Fold cameras directly into smem (fp32; error ~1e-6 vs 1e-3 gate)
    for (int rr = threadIdx.x; rr < NUM_CAMS * 3; rr += TPB) {
        int cam = rr / 3;
        int r = rr - cam * 3;
        const float* E = c2w + cam * 12 + r * 4;
        float R0 = E[0], R1 = E[1], R2 = E[2], t = E[3];
        float f  = K[cam * 9 + 0];
        float cx = K[cam * 9 + 2];
        float cy = K[cam * 9 + 5];
        float invf = 1.0f / f;   // precise div (default prec-div)
        float4 p;
        p.x = R0 * invf;
        p.y = -R1 * invf;
        p.z = -R2 - (cx * R0 - cy * R1) * invf;
        p.w = t;
        scam[rr] = p;
    }
    __syncthreads();

    const int stride = NBLOCKS * TPB;
    int i = blockIdx.x * TPB + threadIdx.x;

    // Main loop: front-batch 4 points' global loads for MLP, then compute+store.
    for (; i + 3 * stride < n; i += 4 * stride) {
        int i0 = i;
        int i1 = i + stride;
        int i2 = i + 2 * stride;
        int i3 = i + 3 * stride;

        int c0 = idx[3 * i0 + 0], y0 = idx[3 * i0 + 1], x0 = idx[3 * i0 + 2];
        int c1 = idx[3 * i1 + 0], y1 = idx[3 * i1 + 1], x1 = idx[3 * i1 + 2];
        int c2 = idx[3 * i2 + 0], y2 = idx[3 * i2 + 1], x2 = idx[3 * i2 + 2];
        int c3 = idx[3 * i3 + 0], y3 = idx[3 * i3 + 1], x3 = idx[3 * i3 + 2];
        float d0 = depth[i0];
        float d1 = depth[i1];
        float d2 = depth[i2];
        float d3 = depth[i3];

        out[i0] = project_one(scam, c0, y0, x0, d0);
        out[i1] = project_one(scam, c1, y1, x1, d1);
        out[i2] = project_one(scam, c2, y2, x2, d2);
        out[i3] = project_one(scam, c3, y3, x3, d3);
    }
    // Remainder
    for (; i < n; i += stride) {
        int c = idx[3 * i + 0];
        int y = idx[3 * i + 1];
        int x = idx[3 * i + 2];
        float d = depth[i];
        out[i] = project_one(scam, c, y, x, d);
    }
}

extern "C" void kernel_launch(void* const* d_in, const int* in_sizes, int n_in,
                              void* d_out, int out_size) {
    // metadata order: point_indices(int32 N*3), depth(f32 N), image_coords(unused),
    //                 camera_to_worlds(f32 C*3*4), intrinsics(f32 C*3*3)
    const int*   idx   = (const int*)d_in[0];
    const float* depth = (const float*)d_in[1];
    const float* c2w   = (const float*)d_in[3];
    const float* K     = (const float*)d_in[4];
    float4* out = (float4*)d_out;
    int n = in_sizes[0] / 3;

    pointgen_kernel<<<NBLOCKS, TPB>>>(idx, depth, c2w, K, out, n);
}